// round 14
// baseline (speedup 1.0000x reference)
#include <cuda_runtime.h>
#include <cuda_bf16.h>
#include <cstdint>

#define VOCAB   50257
#define VPAD    50304               // 393 * 128 (padded rows for W_out split)
#define EMBED   512
#define HIDDEN  1024
#define TSTEPS  2048

// Scratch (allocation-free rule: __device__ globals)
__device__ float    g_xp[TSTEPS * HIDDEN];          // 8 MB
__device__ float    g_hs[TSTEPS * HIDDEN];          // 8 MB
__device__ uint16_t g_hsH[TSTEPS * HIDDEN];         // 4 MB  bf16 hi of hs
__device__ uint16_t g_hsL[TSTEPS * HIDDEN];         // 4 MB  bf16 lo of hs
__device__ uint16_t g_woutH[(size_t)VPAD * HIDDEN]; // 103 MB bf16 hi of W_out
__device__ uint16_t g_woutL[(size_t)VPAD * HIDDEN]; // 103 MB bf16 lo of W_out
__device__ unsigned long long g_bar_cnt;            // monotonic grid barrier

// ===========================================================================
// helpers
// ===========================================================================
__device__ __forceinline__ uint32_t smem_u32(const void* p) {
    uint32_t a;
    asm("{ .reg .u64 t; cvta.to.shared.u64 t, %1; cvt.u32.u64 %0, t; }"
        : "=r"(a) : "l"(p));
    return a;
}
__device__ __forceinline__ uint32_t pack_bf16x2(float lo, float hi) {
    uint32_t r;
    asm("cvt.rn.bf16x2.f32 %0, %1, %2;" : "=r"(r) : "f"(hi), "f"(lo));
    return r;
}
// split float4 into hi (bf16 round) and lo (bf16 of residual)
__device__ __forceinline__ void split4(float4 v, uint2& hi, uint2& lo) {
    uint32_t h0 = pack_bf16x2(v.x, v.y);
    uint32_t h1 = pack_bf16x2(v.z, v.w);
    float fx = __uint_as_float(h0 << 16);
    float fy = __uint_as_float(h0 & 0xFFFF0000u);
    float fz = __uint_as_float(h1 << 16);
    float fw = __uint_as_float(h1 & 0xFFFF0000u);
    uint32_t l0 = pack_bf16x2(v.x - fx, v.y - fy);
    uint32_t l1 = pack_bf16x2(v.z - fz, v.w - fw);
    hi = make_uint2(h0, h1);
    lo = make_uint2(l0, l1);
}

#define LDSM_X4(r0, r1, r2, r3, addr)                                       \
    asm volatile("ldmatrix.sync.aligned.m8n8.x4.shared.b16 {%0,%1,%2,%3}, [%4];" \
                 : "=r"(r0), "=r"(r1), "=r"(r2), "=r"(r3) : "r"(addr))

#define MMA_BF16(c, a0, a1, a2, a3, b0, b1)                                 \
    asm volatile("mma.sync.aligned.m16n8k16.row.col.f32.bf16.bf16.f32 "     \
                 "{%0,%1,%2,%3}, {%4,%5,%6,%7}, {%8,%9}, {%0,%1,%2,%3};"    \
                 : "+f"((c)[0]), "+f"((c)[1]), "+f"((c)[2]), "+f"((c)[3])   \
                 : "r"(a0), "r"(a1), "r"(a2), "r"(a3), "r"(b0), "r"(b1))

#define CP16(dst, src)                                                      \
    asm volatile("cp.async.cg.shared.global [%0], [%1], 16;"                \
                 :: "r"(dst), "l"(src) : "memory")
#define CP_COMMIT()  asm volatile("cp.async.commit_group;" ::: "memory")
#define CP_WAIT1()   asm volatile("cp.async.wait_group 1;" ::: "memory")
#define CP_WAIT0()   asm volatile("cp.async.wait_group 0;" ::: "memory")

// ===========================================================================
// Splitters: fp32 -> (bf16 hi, bf16 lo)
// ===========================================================================
__global__ __launch_bounds__(256)
void split_wout_kernel(const float* __restrict__ W,
                       uint16_t* __restrict__ H, uint16_t* __restrict__ L)
{
    const size_t total4 = (size_t)VPAD * HIDDEN / 4;
    const size_t valid4 = (size_t)VOCAB * HIDDEN / 4;
    for (size_t i = (size_t)blockIdx.x * blockDim.x + threadIdx.x;
         i < total4; i += (size_t)gridDim.x * blockDim.x) {
        float4 v = (i < valid4) ? ((const float4*)W)[i]
                                : make_float4(0.f, 0.f, 0.f, 0.f);
        uint2 hi, lo;
        split4(v, hi, lo);
        ((uint2*)H)[i] = hi;
        ((uint2*)L)[i] = lo;
    }
}

__global__ __launch_bounds__(256)
void split_hs_kernel(const float* __restrict__ S,
                     uint16_t* __restrict__ H, uint16_t* __restrict__ L)
{
    const size_t i = (size_t)blockIdx.x * blockDim.x + threadIdx.x;
    float4 v = ((const float4*)S)[i];
    uint2 hi, lo;
    split4(v, hi, lo);
    ((uint2*)H)[i] = hi;
    ((uint2*)L)[i] = lo;
}

// ===========================================================================
// fp32 SGEMM (NT) — only for the small xp = emb[x] @ W_xh^T GEMM
// ===========================================================================
template <bool GATHER>
__global__ __launch_bounds__(256, 2)
void sgemm_nt_kernel(const float* __restrict__ A,
                     const float* __restrict__ B,
                     const float* __restrict__ bias,
                     float* __restrict__ C,
                     const int* __restrict__ idx,
                     int M, int N, int K)
{
    const int BM = 128, BN = 128, BK = 8;
    __shared__ float As[BK][BM];
    __shared__ float Bs[BK][BN];

    const int tid  = threadIdx.x;
    const int row0 = blockIdx.y * BM;
    const int col0 = blockIdx.x * BN;

    const int lr = tid >> 1;
    const int lc = (tid & 1) * 4;

    const int arow_g = row0 + lr;
    const float* Arow = A + (size_t)(GATHER ? idx[arow_g] : arow_g) * K;

    const int brow_g = col0 + lr;
    const float* Brow = B + (size_t)brow_g * K;
    const bool bvalid = (brow_g < N);

    const int tx = tid & 15;
    const int ty = tid >> 4;

    float acc[8][8];
#pragma unroll
    for (int i = 0; i < 8; i++)
#pragma unroll
        for (int j = 0; j < 8; j++) acc[i][j] = 0.0f;

    for (int k0 = 0; k0 < K; k0 += BK) {
        float4 av = *(const float4*)(Arow + k0 + lc);
        float4 bv = make_float4(0.f, 0.f, 0.f, 0.f);
        if (bvalid) bv = *(const float4*)(Brow + k0 + lc);

        As[lc + 0][lr] = av.x; As[lc + 1][lr] = av.y;
        As[lc + 2][lr] = av.z; As[lc + 3][lr] = av.w;
        Bs[lc + 0][lr] = bv.x; Bs[lc + 1][lr] = bv.y;
        Bs[lc + 2][lr] = bv.z; Bs[lc + 3][lr] = bv.w;
        __syncthreads();

#pragma unroll
        for (int k = 0; k < BK; k++) {
            float af[8], bf[8];
#pragma unroll
            for (int i = 0; i < 8; i++) af[i] = As[k][ty * 8 + i];
#pragma unroll
            for (int j = 0; j < 8; j++) bf[j] = Bs[k][tx * 8 + j];
#pragma unroll
            for (int i = 0; i < 8; i++)
#pragma unroll
                for (int j = 0; j < 8; j++) acc[i][j] += af[i] * bf[j];
        }
        __syncthreads();
    }

#pragma unroll
    for (int i = 0; i < 8; i++) {
        const int row = row0 + ty * 8 + i;
        float* Crow = C + (size_t)row * N;
#pragma unroll
        for (int j = 0; j < 8; j++) {
            const int col = col0 + tx * 8 + j;
            if (col < N) {
                float v = acc[i][j];
                if (bias) v += bias[col];
                Crow[col] = v;
            }
        }
    }
}

// ===========================================================================
// Recurrence — exact R11 version (best measured): 64 blocks x 512 threads,
// W_hh rows in registers, replay-safe monotonic-counter grid barrier.
// ===========================================================================
#define RNN_NB 64
#define RNN_NT 512

__global__ __launch_bounds__(RNN_NT, 1)
void rnn_recurrence_kernel(const float* __restrict__ xp,
                           const float* __restrict__ W_hh,
                           const float* __restrict__ b_hh,
                           float* __restrict__ hs,
                           float* __restrict__ h_final)
{
    __shared__ float hsm[HIDDEN];

    const int tid  = threadIdx.x;
    const int warp = tid >> 5;
    const int lane = tid & 31;
    const int row  = blockIdx.x * 16 + warp;

    float w[32];
    const float* Wrow = W_hh + (size_t)row * HIDDEN;
#pragma unroll
    for (int k = 0; k < 32; k++) w[k] = Wrow[lane + 32 * k];
    const float bias = b_hh[row];

    const unsigned long long TOTAL = (unsigned long long)TSTEPS * RNN_NB;
    unsigned long long base = 0;

    for (int t = 0; t < TSTEPS; t++) {
        if (t == 0) {
            hsm[tid]       = 0.0f;
            hsm[tid + 512] = 0.0f;
        } else {
            const float* hprev = hs + (size_t)(t - 1) * HIDDEN;
            hsm[tid]       = hprev[tid];
            hsm[tid + 512] = hprev[tid + 512];
        }
        __syncthreads();

        float acc = 0.0f;
#pragma unroll
        for (int k = 0; k < 32; k++) acc += w[k] * hsm[lane + 32 * k];
#pragma unroll
        for (int off = 16; off > 0; off >>= 1)
            acc += __shfl_down_sync(0xffffffffu, acc, off);

        if (lane == 0) {
            float v = tanhf(acc + xp[(size_t)t * HIDDEN + row] + bias);
            hs[(size_t)t * HIDDEN + row] = v;
            if (t == TSTEPS - 1) h_final[row] = v;
        }
        __syncthreads();

        if (tid == 0) {
            __threadfence();
            unsigned long long tk = atomicAdd(&g_bar_cnt, 1ULL);
            if (t == 0) base = (tk / TOTAL) * TOTAL;
            const unsigned long long target =
                base + (unsigned long long)(t + 1) * RNN_NB;
            while (*(volatile unsigned long long*)&g_bar_cnt < target) { }
            __threadfence();
        }
        __syncthreads();
    }
}

// ===========================================================================
// Logits GEMM v3: C = hs @ W_out^T + b_out, bf16 hi/lo PRE-SPLIT operands.
// Pure cp.async (LDGSTS) gmem->smem pipeline, 2 stages, no in-loop
// conversion, no B bounds checks (W_out split is zero-padded to VPAD rows).
// CTA tile 128x128, BK=32, PITCH=80 ldmatrix layout, 2 CTAs/SM.
// ===========================================================================
#define TCB_M 128
#define TCB_N 128
#define TCB_K 32
#define NCH   (HIDDEN / TCB_K)            // 32
#define PITCH 80                          // 64B data + 16B pad per 32-elem row
#define MATB  (TCB_M * PITCH)             // 10240 per matrix tile
#define BUFB  (4 * MATB)                  // AH, AL, BH, BL = 40960
#define MMA_SMEM (2 * BUFB + 512)         // 82432 -> 2 CTAs/SM

__global__ __launch_bounds__(256, 2)
void mma_logits_kernel(const uint16_t* __restrict__ AH,  // hsH  [2048,1024]
                       const uint16_t* __restrict__ AL,  // hsL
                       const uint16_t* __restrict__ BH,  // woutH [VPAD,1024]
                       const uint16_t* __restrict__ BL,  // woutL
                       const float* __restrict__ bias,   // [VOCAB]
                       float* __restrict__ C)            // [2048,VOCAB]
{
    extern __shared__ char sm[];
    float* bias_s = (float*)(sm + 2 * BUFB);
    const uint32_t sbase = smem_u32(sm);

    const int tid   = threadIdx.x;
    const int wid   = tid >> 5;
    const int lane  = tid & 31;
    const int warpm = wid >> 2;            // 0..1 -> 64-row slab
    const int warpn = wid & 3;             // 0..3 -> 32-col slab
    const int row0  = blockIdx.x * TCB_M;
    const int col0  = blockIdx.y * TCB_N;

    if (tid < TCB_N) {
        int c = col0 + tid;
        bias_s[tid] = (c < VOCAB) ? bias[c] : 0.0f;
    }

    float acc[4][4][4];
#pragma unroll
    for (int i = 0; i < 4; i++)
#pragma unroll
        for (int j = 0; j < 4; j++)
#pragma unroll
            for (int r = 0; r < 4; r++) acc[i][j][r] = 0.0f;

    // one chunk = 128 rows x 32 bf16 per matrix; per thread: 8 cp.async x16B
    auto load_chunk = [&](int k, int buf) {
        const uint32_t base = sbase + buf * BUFB;
        const int k0 = k * TCB_K;
#pragma unroll
        for (int i = 0; i < 2; i++) {
            const int lin = tid + 256 * i;          // 0..511
            const int r = lin >> 2;                 // 0..127
            const int c = lin & 3;                  // 16B chunk in row
            const uint32_t doff = (uint32_t)(r * PITCH + c * 16);
            const size_t aoff = (size_t)(row0 + r) * HIDDEN + k0 + c * 8;
            const size_t boff = (size_t)(col0 + r) * HIDDEN + k0 + c * 8;
            CP16(base + doff,            AH + aoff);
            CP16(base + MATB + doff,     AL + aoff);
            CP16(base + 2 * MATB + doff, BH + boff);
            CP16(base + 3 * MATB + doff, BL + boff);
        }
        CP_COMMIT();
    };

    auto mma_chunk = [&](int buf) {
        const uint32_t base = sbase + buf * BUFB;
        const uint32_t lrow = lane & 15;
        const uint32_t lhalf = (lane >> 4) * 16;
#pragma unroll
        for (int s = 0; s < 2; s++) {               // two k16 slices
            uint32_t ah[4][4], al[4][4], bh[2][4], bl[2][4];
#pragma unroll
            for (int mf = 0; mf < 4; mf++) {
                uint32_t ad = base + (warpm * 64 + mf * 16 + lrow) * PITCH
                            + s * 32 + lhalf;
                LDSM_X4(ah[mf][0], ah[mf][1], ah[mf][2], ah[mf][3], ad);
                LDSM_X4(al[mf][0], al[mf][1], al[mf][2], al[mf][3], ad + MATB);
            }
#pragma unroll
            for (int p = 0; p < 2; p++) {
                uint32_t bd = base + 2 * MATB
                            + (warpn * 32 + p * 16 + lrow) * PITCH
                            + s * 32 + lhalf;
                LDSM_X4(bh[p][0], bh[p][1], bh[p][2], bh[p][3], bd);
                LDSM_X4(bl[p][0], bl[p][1], bl[p][2], bl[p][3], bd + MATB);
            }
            // product-type OUTER: same-acc reuse distance = 16 MMAs
#pragma unroll
            for (int mf = 0; mf < 4; mf++)
#pragma unroll
                for (int nf = 0; nf < 4; nf++) {
                    const int p = nf >> 1, q = nf & 1;
                    MMA_BF16(acc[mf][nf], ah[mf][0], ah[mf][1], ah[mf][2], ah[mf][3],
                             bh[p][q], bh[p][q + 2]);
                }
#pragma unroll
            for (int mf = 0; mf < 4; mf++)
#pragma unroll
                for (int nf = 0; nf < 4; nf++) {
                    const int p = nf >> 1, q = nf & 1;
                    MMA_BF16(acc[mf][nf], al[mf][0], al[mf][1], al[mf][2], al[mf][3],
                             bh[p][q], bh[p][q + 2]);
                }
#pragma unroll
            for (int mf = 0; mf < 4; mf++)
#pragma unroll
                for (int nf = 0; nf < 4; nf++) {
                    const int p = nf >> 1, q = nf & 1;
                    MMA_BF16(acc[mf][nf], ah[mf][0], ah[mf][1], ah[mf][2], ah[mf][3],
                             bl[p][q], bl[p][q + 2]);
                }
        }
    };

    load_chunk(0, 0);
    load_chunk(1, 1);

#pragma unroll 1
    for (int k = 0; k < NCH; k++) {
        if (k + 1 < NCH) { CP_WAIT1(); } else { CP_WAIT0(); }
        __syncthreads();
        mma_chunk(k & 1);
        __syncthreads();                 // all warps done reading this buffer
        if (k + 2 < NCH) load_chunk(k + 2, k & 1);
    }

    // epilogue: acc frag m16n8 -> (row = lane/4 [+8], col = 2*(lane%4)+{0,1})
#pragma unroll
    for (int mf = 0; mf < 4; mf++) {
#pragma unroll
        for (int nf = 0; nf < 4; nf++) {
            const int mrow = row0 + warpm * 64 + mf * 16 + (lane >> 2);
            const int ncl  = warpn * 32 + nf * 8 + (lane & 3) * 2;
            const int col  = col0 + ncl;
            float* C0 = C + (size_t)mrow * VOCAB;
            float* C1 = C + (size_t)(mrow + 8) * VOCAB;
            if (col < VOCAB) {
                const float bv = bias_s[ncl];
                C0[col] = acc[mf][nf][0] + bv;
                C1[col] = acc[mf][nf][2] + bv;
            }
            if (col + 1 < VOCAB) {
                const float bv = bias_s[ncl + 1];
                C0[col + 1] = acc[mf][nf][1] + bv;
                C1[col + 1] = acc[mf][nf][3] + bv;
            }
        }
    }
}

// ===========================================================================
// launch
// ===========================================================================
extern "C" void kernel_launch(void* const* d_in, const int* in_sizes, int n_in,
                              void* d_out, int out_size)
{
    const int*   x     = (const int*)  d_in[0];
    const float* emb   = (const float*)d_in[1];
    const float* W_xh  = (const float*)d_in[2];
    const float* W_hh  = (const float*)d_in[3];
    const float* b_hh  = (const float*)d_in[4];
    const float* W_out = (const float*)d_in[5];
    const float* b_out = (const float*)d_in[6];

    float* logits  = (float*)d_out;
    float* h_final = (float*)d_out + (size_t)TSTEPS * VOCAB;

    float *xp, *hs;
    uint16_t *hsH, *hsL, *woutH, *woutL;
    cudaGetSymbolAddress((void**)&xp,    g_xp);
    cudaGetSymbolAddress((void**)&hs,    g_hs);
    cudaGetSymbolAddress((void**)&hsH,   g_hsH);
    cudaGetSymbolAddress((void**)&hsL,   g_hsL);
    cudaGetSymbolAddress((void**)&woutH, g_woutH);
    cudaGetSymbolAddress((void**)&woutL, g_woutL);

    // 0) split W_out -> bf16 hi/lo (independent; overlaps nothing critical)
    split_wout_kernel<<<1184, 256>>>(W_out, woutH, woutL);

    // 1) xp = emb[x] @ W_xh^T      (M=2048, N=1024, K=512)
    {
        dim3 grid(HIDDEN / 128, TSTEPS / 128);
        sgemm_nt_kernel<true><<<grid, 256>>>(emb, W_xh, nullptr, xp, x,
                                             TSTEPS, HIDDEN, EMBED);
    }

    // 2) sequential recurrence -> hs, h_final
    rnn_recurrence_kernel<<<RNN_NB, RNN_NT>>>(xp, W_hh, b_hh, hs, h_final);

    // 2b) split hs -> bf16 hi/lo
    split_hs_kernel<<<TSTEPS * HIDDEN / 4 / 256, 256>>>(hs, hsH, hsL);

    // 3) logits = hsHL @ woutHL^T + b_out  (cp.async bf16 MMA pipeline)
    {
        cudaFuncSetAttribute(mma_logits_kernel,
                             cudaFuncAttributeMaxDynamicSharedMemorySize,
                             MMA_SMEM);
        dim3 grid(TSTEPS / TCB_M, VPAD / TCB_N);   // 16 x 393
        mma_logits_kernel<<<grid, 256, MMA_SMEM>>>(hsH, hsL, woutH, woutL,
                                                   b_out, logits);
    }
}

// round 15
// speedup vs baseline: 1.3644x; 1.3644x over previous
#include <cuda_runtime.h>
#include <cuda_bf16.h>
#include <cstdint>

#define VOCAB   50257
#define EMBED   512
#define HIDDEN  1024
#define TSTEPS  2048

// Scratch (allocation-free rule: __device__ globals)
__device__ float g_xp[TSTEPS * HIDDEN];   // 8 MB: input projections
__device__ float g_hs[TSTEPS * HIDDEN];   // 8 MB: hidden states per step

// ===========================================================================
// helpers
// ===========================================================================
__device__ __forceinline__ uint32_t smem_u32(const void* p) {
    uint32_t a;
    asm("{ .reg .u64 t; cvta.to.shared.u64 t, %1; cvt.u32.u64 %0, t; }"
        : "=r"(a) : "l"(p));
    return a;
}

// pack two fp32 -> bf16x2 (first arg -> low half)
__device__ __forceinline__ uint32_t pack_bf16x2(float lo, float hi) {
    uint32_t r;
    asm("cvt.rn.bf16x2.f32 %0, %1, %2;" : "=r"(r) : "f"(hi), "f"(lo));
    return r;
}
// split float4 into hi (bf16 round) and lo (bf16 of residual)
__device__ __forceinline__ void split4(float4 v, uint2& hi, uint2& lo) {
    uint32_t h0 = pack_bf16x2(v.x, v.y);
    uint32_t h1 = pack_bf16x2(v.z, v.w);
    float fx = __uint_as_float(h0 << 16);
    float fy = __uint_as_float(h0 & 0xFFFF0000u);
    float fz = __uint_as_float(h1 << 16);
    float fw = __uint_as_float(h1 & 0xFFFF0000u);
    uint32_t l0 = pack_bf16x2(v.x - fx, v.y - fy);
    uint32_t l1 = pack_bf16x2(v.z - fz, v.w - fw);
    hi = make_uint2(h0, h1);
    lo = make_uint2(l0, l1);
}

#define LDSM_X4(r0, r1, r2, r3, addr)                                       \
    asm volatile("ldmatrix.sync.aligned.m8n8.x4.shared.b16 {%0,%1,%2,%3}, [%4];" \
                 : "=r"(r0), "=r"(r1), "=r"(r2), "=r"(r3) : "r"(addr))

#define MMA_BF16(c, a0, a1, a2, a3, b0, b1)                                 \
    asm volatile("mma.sync.aligned.m16n8k16.row.col.f32.bf16.bf16.f32 "     \
                 "{%0,%1,%2,%3}, {%4,%5,%6,%7}, {%8,%9}, {%0,%1,%2,%3};"    \
                 : "+f"((c)[0]), "+f"((c)[1]), "+f"((c)[2]), "+f"((c)[3])   \
                 : "r"(a0), "r"(a1), "r"(a2), "r"(a3), "r"(b0), "r"(b1))

// ===========================================================================
// fp32 SGEMM (NT) — used only for the small xp = emb[x] @ W_xh^T GEMM
// ===========================================================================
template <bool GATHER>
__global__ __launch_bounds__(256, 2)
void sgemm_nt_kernel(const float* __restrict__ A,
                     const float* __restrict__ B,
                     const float* __restrict__ bias,
                     float* __restrict__ C,
                     const int* __restrict__ idx,
                     int M, int N, int K)
{
    const int BM = 128, BN = 128, BK = 8;
    __shared__ float As[BK][BM];
    __shared__ float Bs[BK][BN];

    const int tid  = threadIdx.x;
    const int row0 = blockIdx.y * BM;
    const int col0 = blockIdx.x * BN;

    const int lr = tid >> 1;
    const int lc = (tid & 1) * 4;

    const int arow_g = row0 + lr;
    const float* Arow = A + (size_t)(GATHER ? idx[arow_g] : arow_g) * K;

    const int brow_g = col0 + lr;
    const float* Brow = B + (size_t)brow_g * K;
    const bool bvalid = (brow_g < N);

    const int tx = tid & 15;
    const int ty = tid >> 4;

    float acc[8][8];
#pragma unroll
    for (int i = 0; i < 8; i++)
#pragma unroll
        for (int j = 0; j < 8; j++) acc[i][j] = 0.0f;

    for (int k0 = 0; k0 < K; k0 += BK) {
        float4 av = *(const float4*)(Arow + k0 + lc);
        float4 bv = make_float4(0.f, 0.f, 0.f, 0.f);
        if (bvalid) bv = *(const float4*)(Brow + k0 + lc);

        As[lc + 0][lr] = av.x; As[lc + 1][lr] = av.y;
        As[lc + 2][lr] = av.z; As[lc + 3][lr] = av.w;
        Bs[lc + 0][lr] = bv.x; Bs[lc + 1][lr] = bv.y;
        Bs[lc + 2][lr] = bv.z; Bs[lc + 3][lr] = bv.w;
        __syncthreads();

#pragma unroll
        for (int k = 0; k < BK; k++) {
            float af[8], bf[8];
#pragma unroll
            for (int i = 0; i < 8; i++) af[i] = As[k][ty * 8 + i];
#pragma unroll
            for (int j = 0; j < 8; j++) bf[j] = Bs[k][tx * 8 + j];
#pragma unroll
            for (int i = 0; i < 8; i++)
#pragma unroll
                for (int j = 0; j < 8; j++) acc[i][j] += af[i] * bf[j];
        }
        __syncthreads();
    }

#pragma unroll
    for (int i = 0; i < 8; i++) {
        const int row = row0 + ty * 8 + i;
        float* Crow = C + (size_t)row * N;
#pragma unroll
        for (int j = 0; j < 8; j++) {
            const int col = col0 + tx * 8 + j;
            if (col < N) {
                float v = acc[i][j];
                if (bias) v += bias[col];
                Crow[col] = v;
            }
        }
    }
}

// ===========================================================================
// Recurrence v3: SAME geometry as R11 (64 blocks x 512 threads, W_hh rows
// in registers) — the ONLY changes vs R11 are:
//   (a) grid barrier: per-block flag words in DISTINCT 128B L2 lines with
//       plain release stores (removes the 64-arrival same-address atomicAdd
//       queue, ~n_conc*32*0.854 cyc/step), warp 0 polls 2 flags per lane;
//   (b) 4-way ILP dot product (breaks the serial 32-FMA dependency chain).
// Flags are monotonic and block-owned -> graph-replay-safe: every launch
// advances every flag by exactly TSTEPS, so at entry all flags are equal
// and base = own flag.
// ===========================================================================
#define RNN_NB 64
#define RNN_NT 512

__device__ volatile unsigned g_flags[RNN_NB * 32];   // stride 32 ints = 128B

__global__ __launch_bounds__(RNN_NT, 1)
void rnn_recurrence_kernel(const float* __restrict__ xp,
                           const float* __restrict__ W_hh,
                           const float* __restrict__ b_hh,
                           float* __restrict__ hs,
                           float* __restrict__ h_final)
{
    __shared__ float hsm[HIDDEN];

    const int tid  = threadIdx.x;
    const int warp = tid >> 5;
    const int lane = tid & 31;
    const int row  = blockIdx.x * 16 + warp;

    float w[32];
    const float* Wrow = W_hh + (size_t)row * HIDDEN;
#pragma unroll
    for (int k = 0; k < 32; k++) w[k] = Wrow[lane + 32 * k];
    const float bias = b_hh[row];

    // quiescent at entry: every flag has advanced by the same amount
    const unsigned base = g_flags[blockIdx.x * 32];

    for (int t = 0; t < TSTEPS; t++) {
        if (t == 0) {
            hsm[tid]       = 0.0f;
            hsm[tid + 512] = 0.0f;
        } else {
            const float* hprev = hs + (size_t)(t - 1) * HIDDEN;
            hsm[tid]       = hprev[tid];
            hsm[tid + 512] = hprev[tid + 512];
        }
        __syncthreads();

        const float xv = xp[(size_t)t * HIDDEN + row];

        // 4-way ILP dot product
        float a0 = 0.f, a1 = 0.f, a2 = 0.f, a3 = 0.f;
#pragma unroll
        for (int k = 0; k < 8; k++) {
            a0 += w[4 * k + 0] * hsm[lane + 32 * (4 * k + 0)];
            a1 += w[4 * k + 1] * hsm[lane + 32 * (4 * k + 1)];
            a2 += w[4 * k + 2] * hsm[lane + 32 * (4 * k + 2)];
            a3 += w[4 * k + 3] * hsm[lane + 32 * (4 * k + 3)];
        }
        float acc = (a0 + a1) + (a2 + a3);
#pragma unroll
        for (int off = 16; off > 0; off >>= 1)
            acc += __shfl_down_sync(0xffffffffu, acc, off);

        if (lane == 0) {
            float v = tanhf(acc + xv + bias);
            hs[(size_t)t * HIDDEN + row] = v;
            if (t == TSTEPS - 1) h_final[row] = v;
        }
        __syncthreads();          // all 16 rows of this block written

        // ---- grid barrier: own release-store + parallel poll ----
        if (tid == 0) {
            __threadfence();                              // publish hs[t]
            g_flags[blockIdx.x * 32] = base + t + 1;      // release own flag
        }
        if (tid < 32) {                                   // warp 0 polls all 64
            const unsigned tgt = base + t + 1;
            while (true) {
                unsigned v0 = g_flags[lane * 32];
                unsigned v1 = g_flags[(lane + 32) * 32];
                if (__all_sync(0xffffffffu, (v0 >= tgt) && (v1 >= tgt))) break;
            }
            __threadfence();                              // acquire peers
        }
        __syncthreads();
    }
}

// ===========================================================================
// Logits GEMM — EXACT R11 kernel (best measured: 7227us total).
// C[2048,50257] = hs @ W_out^T + b_out, bf16 hi/lo split, CTA tile 128x128,
// BK=32, PITCH=80, register prefetch, grouped 3-MMA per (mf,nf).
// ===========================================================================
#define TCB_M 128
#define TCB_N 128
#define TCB_K 32
#define NCH   (HIDDEN / TCB_K)            // 32
#define PITCH 80                          // 64B data + 16B pad per 32-elem row
#define MATB  (TCB_M * PITCH)             // 10240 bytes per matrix tile
#define BUFB  (4 * MATB)                  // AH, AL, BH, BL
#define MMA_SMEM (2 * BUFB + 512)         // + bias staging

__global__ __launch_bounds__(256, 1)
void mma_logits_kernel(const float* __restrict__ A,    // hs    [2048,1024]
                       const float* __restrict__ B,    // W_out [50257,1024]
                       const float* __restrict__ bias, // [50257]
                       float* __restrict__ C)          // [2048,50257]
{
    extern __shared__ char sm[];
    float* bias_s = (float*)(sm + 2 * BUFB);
    const uint32_t sbase = smem_u32(sm);

    const int tid   = threadIdx.x;
    const int wid   = tid >> 5;
    const int lane  = tid & 31;
    const int warpm = wid >> 2;            // 0..1 -> 64-row slab
    const int warpn = wid & 3;             // 0..3 -> 32-col slab
    const int row0  = blockIdx.x * TCB_M;
    const int col0  = blockIdx.y * TCB_N;

    if (tid < TCB_N) {
        int c = col0 + tid;
        bias_s[tid] = (c < VOCAB) ? bias[c] : 0.0f;
    }

    const float* Abase = A + (size_t)row0 * HIDDEN;
    const float* Bbase = B + (size_t)col0 * HIDDEN;

    float acc[4][4][4];
#pragma unroll
    for (int i = 0; i < 4; i++)
#pragma unroll
        for (int j = 0; j < 4; j++)
#pragma unroll
            for (int r = 0; r < 4; r++) acc[i][j][r] = 0.0f;

    float4 aR[4], bR[4];

    auto ldg_chunk = [&](int k) {
        const int k0 = k * TCB_K;
#pragma unroll
        for (int i = 0; i < 4; i++) {
            int lin = tid + 256 * i;
            int r = lin >> 3, c4 = lin & 7;
            aR[i] = *(const float4*)(Abase + (size_t)r * HIDDEN + k0 + c4 * 4);
            if (col0 + r < VOCAB)
                bR[i] = *(const float4*)(Bbase + (size_t)r * HIDDEN + k0 + c4 * 4);
            else
                bR[i] = make_float4(0.f, 0.f, 0.f, 0.f);
        }
    };

    auto sts_chunk = [&](int buf) {
        char* base = sm + buf * BUFB;
#pragma unroll
        for (int i = 0; i < 4; i++) {
            int lin = tid + 256 * i;
            int r = lin >> 3, c4 = lin & 7;
            int off = r * PITCH + c4 * 8;
            uint2 hi, lo;
            split4(aR[i], hi, lo);
            *(uint2*)(base + off)        = hi;
            *(uint2*)(base + MATB + off) = lo;
            split4(bR[i], hi, lo);
            *(uint2*)(base + 2 * MATB + off) = hi;
            *(uint2*)(base + 3 * MATB + off) = lo;
        }
    };

    auto mma_chunk = [&](int buf) {
        const uint32_t base = sbase + buf * BUFB;
        const uint32_t lrow = lane & 15;
        const uint32_t lhalf = (lane >> 4) * 16;
#pragma unroll
        for (int s = 0; s < 2; s++) {
            uint32_t ah[4][4], al[4][4], bh[2][4], bl[2][4];
#pragma unroll
            for (int mf = 0; mf < 4; mf++) {
                uint32_t ad = base + (warpm * 64 + mf * 16 + lrow) * PITCH
                            + s * 32 + lhalf;
                LDSM_X4(ah[mf][0], ah[mf][1], ah[mf][2], ah[mf][3], ad);
                LDSM_X4(al[mf][0], al[mf][1], al[mf][2], al[mf][3], ad + MATB);
            }
#pragma unroll
            for (int p = 0; p < 2; p++) {
                uint32_t bd = base + 2 * MATB
                            + (warpn * 32 + p * 16 + lrow) * PITCH
                            + s * 32 + lhalf;
                LDSM_X4(bh[p][0], bh[p][1], bh[p][2], bh[p][3], bd);
                LDSM_X4(bl[p][0], bl[p][1], bl[p][2], bl[p][3], bd + MATB);
            }
#pragma unroll
            for (int mf = 0; mf < 4; mf++) {
#pragma unroll
                for (int nf = 0; nf < 4; nf++) {
                    const int p = nf >> 1, q = nf & 1;
                    uint32_t b0h = bh[p][q], b1h = bh[p][q + 2];
                    uint32_t b0l = bl[p][q], b1l = bl[p][q + 2];
                    MMA_BF16(acc[mf][nf], ah[mf][0], ah[mf][1], ah[mf][2], ah[mf][3], b0h, b1h);
                    MMA_BF16(acc[mf][nf], al[mf][0], al[mf][1], al[mf][2], al[mf][3], b0h, b1h);
                    MMA_BF16(acc[mf][nf], ah[mf][0], ah[mf][1], ah[mf][2], ah[mf][3], b0l, b1l);
                }
            }
        }
    };

    ldg_chunk(0);
    sts_chunk(0);
    __syncthreads();

#pragma unroll 1
    for (int k = 0; k < NCH; k++) {
        if (k + 1 < NCH) ldg_chunk(k + 1);     // LDG overlapped with MMA
        mma_chunk(k & 1);
        if (k + 1 < NCH) sts_chunk((k + 1) & 1);
        __syncthreads();
    }

    // epilogue: acc frag m16n8 -> (row = lane/4 [+8], col = 2*(lane%4)+{0,1})
#pragma unroll
    for (int mf = 0; mf < 4; mf++) {
#pragma unroll
        for (int nf = 0; nf < 4; nf++) {
            const int mrow = row0 + warpm * 64 + mf * 16 + (lane >> 2);
            const int ncl  = warpn * 32 + nf * 8 + (lane & 3) * 2;
            const int col  = col0 + ncl;
            float* C0 = C + (size_t)mrow * VOCAB;
            float* C1 = C + (size_t)(mrow + 8) * VOCAB;
            if (col < VOCAB) {
                const float bv = bias_s[ncl];
                C0[col] = acc[mf][nf][0] + bv;
                C1[col] = acc[mf][nf][2] + bv;
            }
            if (col + 1 < VOCAB) {
                const float bv = bias_s[ncl + 1];
                C0[col + 1] = acc[mf][nf][1] + bv;
                C1[col + 1] = acc[mf][nf][3] + bv;
            }
        }
    }
}

// ===========================================================================
// launch
// ===========================================================================
extern "C" void kernel_launch(void* const* d_in, const int* in_sizes, int n_in,
                              void* d_out, int out_size)
{
    const int*   x     = (const int*)  d_in[0];
    const float* emb   = (const float*)d_in[1];
    const float* W_xh  = (const float*)d_in[2];
    const float* W_hh  = (const float*)d_in[3];
    const float* b_hh  = (const float*)d_in[4];
    const float* W_out = (const float*)d_in[5];
    const float* b_out = (const float*)d_in[6];

    float* logits  = (float*)d_out;
    float* h_final = (float*)d_out + (size_t)TSTEPS * VOCAB;

    float *xp, *hs;
    cudaGetSymbolAddress((void**)&xp, g_xp);
    cudaGetSymbolAddress((void**)&hs, g_hs);

    // 1) xp = emb[x] @ W_xh^T      (M=2048, N=1024, K=512)
    {
        dim3 grid(HIDDEN / 128, TSTEPS / 128);
        sgemm_nt_kernel<true><<<grid, 256>>>(emb, W_xh, nullptr, xp, x,
                                             TSTEPS, HIDDEN, EMBED);
    }

    // 2) sequential recurrence -> hs, h_final   (flag barrier + ILP4)
    rnn_recurrence_kernel<<<RNN_NB, RNN_NT>>>(xp, W_hh, b_hh, hs, h_final);

    // 3) logits = hs @ W_out^T + b_out  (exact R11 bf16 MMA kernel)
    {
        cudaFuncSetAttribute(mma_logits_kernel,
                             cudaFuncAttributeMaxDynamicSharedMemorySize,
                             MMA_SMEM);
        dim3 grid(TSTEPS / TCB_M, (VOCAB + TCB_N - 1) / TCB_N); // 16 x 393
        mma_logits_kernel<<<grid, 256, MMA_SMEM>>>(hs, W_out, b_out, logits);
    }
}

// round 16
// speedup vs baseline: 1.3820x; 1.0129x over previous
#include <cuda_runtime.h>
#include <cuda_bf16.h>
#include <cstdint>

#define VOCAB   50257
#define EMBED   512
#define HIDDEN  1024
#define TSTEPS  2048

// Scratch (allocation-free rule: __device__ globals)
__device__ float g_xp[TSTEPS * HIDDEN];   // 8 MB: input projections
__device__ float g_hs[TSTEPS * HIDDEN];   // 8 MB: hidden states per step
__device__ unsigned long long g_bar_cnt;  // monotonic grid-barrier counter

// ===========================================================================
// helpers
// ===========================================================================
__device__ __forceinline__ uint32_t smem_u32(const void* p) {
    uint32_t a;
    asm("{ .reg .u64 t; cvta.to.shared.u64 t, %1; cvt.u32.u64 %0, t; }"
        : "=r"(a) : "l"(p));
    return a;
}

// pack two fp32 -> bf16x2 (first arg -> low half)
__device__ __forceinline__ uint32_t pack_bf16x2(float lo, float hi) {
    uint32_t r;
    asm("cvt.rn.bf16x2.f32 %0, %1, %2;" : "=r"(r) : "f"(hi), "f"(lo));
    return r;
}
// split float4 into hi (bf16 round) and lo (bf16 of residual)
__device__ __forceinline__ void split4(float4 v, uint2& hi, uint2& lo) {
    uint32_t h0 = pack_bf16x2(v.x, v.y);
    uint32_t h1 = pack_bf16x2(v.z, v.w);
    float fx = __uint_as_float(h0 << 16);
    float fy = __uint_as_float(h0 & 0xFFFF0000u);
    float fz = __uint_as_float(h1 << 16);
    float fw = __uint_as_float(h1 & 0xFFFF0000u);
    uint32_t l0 = pack_bf16x2(v.x - fx, v.y - fy);
    uint32_t l1 = pack_bf16x2(v.z - fz, v.w - fw);
    hi = make_uint2(h0, h1);
    lo = make_uint2(l0, l1);
}

#define LDSM_X4(r0, r1, r2, r3, addr)                                       \
    asm volatile("ldmatrix.sync.aligned.m8n8.x4.shared.b16 {%0,%1,%2,%3}, [%4];" \
                 : "=r"(r0), "=r"(r1), "=r"(r2), "=r"(r3) : "r"(addr))

#define MMA_BF16(c, a0, a1, a2, a3, b0, b1)                                 \
    asm volatile("mma.sync.aligned.m16n8k16.row.col.f32.bf16.bf16.f32 "     \
                 "{%0,%1,%2,%3}, {%4,%5,%6,%7}, {%8,%9}, {%0,%1,%2,%3};"    \
                 : "+f"((c)[0]), "+f"((c)[1]), "+f"((c)[2]), "+f"((c)[3])   \
                 : "r"(a0), "r"(a1), "r"(a2), "r"(a3), "r"(b0), "r"(b1))

// ===========================================================================
// fp32 SGEMM (NT) — used only for the small xp = emb[x] @ W_xh^T GEMM
// ===========================================================================
template <bool GATHER>
__global__ __launch_bounds__(256, 2)
void sgemm_nt_kernel(const float* __restrict__ A,
                     const float* __restrict__ B,
                     const float* __restrict__ bias,
                     float* __restrict__ C,
                     const int* __restrict__ idx,
                     int M, int N, int K)
{
    const int BM = 128, BN = 128, BK = 8;
    __shared__ float As[BK][BM];
    __shared__ float Bs[BK][BN];

    const int tid  = threadIdx.x;
    const int row0 = blockIdx.y * BM;
    const int col0 = blockIdx.x * BN;

    const int lr = tid >> 1;
    const int lc = (tid & 1) * 4;

    const int arow_g = row0 + lr;
    const float* Arow = A + (size_t)(GATHER ? idx[arow_g] : arow_g) * K;

    const int brow_g = col0 + lr;
    const float* Brow = B + (size_t)brow_g * K;
    const bool bvalid = (brow_g < N);

    const int tx = tid & 15;
    const int ty = tid >> 4;

    float acc[8][8];
#pragma unroll
    for (int i = 0; i < 8; i++)
#pragma unroll
        for (int j = 0; j < 8; j++) acc[i][j] = 0.0f;

    for (int k0 = 0; k0 < K; k0 += BK) {
        float4 av = *(const float4*)(Arow + k0 + lc);
        float4 bv = make_float4(0.f, 0.f, 0.f, 0.f);
        if (bvalid) bv = *(const float4*)(Brow + k0 + lc);

        As[lc + 0][lr] = av.x; As[lc + 1][lr] = av.y;
        As[lc + 2][lr] = av.z; As[lc + 3][lr] = av.w;
        Bs[lc + 0][lr] = bv.x; Bs[lc + 1][lr] = bv.y;
        Bs[lc + 2][lr] = bv.z; Bs[lc + 3][lr] = bv.w;
        __syncthreads();

#pragma unroll
        for (int k = 0; k < BK; k++) {
            float af[8], bf[8];
#pragma unroll
            for (int i = 0; i < 8; i++) af[i] = As[k][ty * 8 + i];
#pragma unroll
            for (int j = 0; j < 8; j++) bf[j] = Bs[k][tx * 8 + j];
#pragma unroll
            for (int i = 0; i < 8; i++)
#pragma unroll
                for (int j = 0; j < 8; j++) acc[i][j] += af[i] * bf[j];
        }
        __syncthreads();
    }

#pragma unroll
    for (int i = 0; i < 8; i++) {
        const int row = row0 + ty * 8 + i;
        float* Crow = C + (size_t)row * N;
#pragma unroll
        for (int j = 0; j < 8; j++) {
            const int col = col0 + tx * 8 + j;
            if (col < N) {
                float v = acc[i][j];
                if (bias) v += bias[col];
                Crow[col] = v;
            }
        }
    }
}

// ===========================================================================
// Recurrence — EXACT R11 version (best measured): 64 blocks x 512 threads,
// W_hh rows in registers, replay-safe monotonic-counter grid barrier.
// ===========================================================================
#define RNN_NB 64
#define RNN_NT 512

__global__ __launch_bounds__(RNN_NT, 1)
void rnn_recurrence_kernel(const float* __restrict__ xp,
                           const float* __restrict__ W_hh,
                           const float* __restrict__ b_hh,
                           float* __restrict__ hs,
                           float* __restrict__ h_final)
{
    __shared__ float hsm[HIDDEN];

    const int tid  = threadIdx.x;
    const int warp = tid >> 5;
    const int lane = tid & 31;
    const int row  = blockIdx.x * 16 + warp;

    float w[32];
    const float* Wrow = W_hh + (size_t)row * HIDDEN;
#pragma unroll
    for (int k = 0; k < 32; k++) w[k] = Wrow[lane + 32 * k];
    const float bias = b_hh[row];

    const unsigned long long TOTAL = (unsigned long long)TSTEPS * RNN_NB;
    unsigned long long base = 0;

    for (int t = 0; t < TSTEPS; t++) {
        if (t == 0) {
            hsm[tid]       = 0.0f;
            hsm[tid + 512] = 0.0f;
        } else {
            const float* hprev = hs + (size_t)(t - 1) * HIDDEN;
            hsm[tid]       = hprev[tid];
            hsm[tid + 512] = hprev[tid + 512];
        }
        __syncthreads();

        float acc = 0.0f;
#pragma unroll
        for (int k = 0; k < 32; k++) acc += w[k] * hsm[lane + 32 * k];
#pragma unroll
        for (int off = 16; off > 0; off >>= 1)
            acc += __shfl_down_sync(0xffffffffu, acc, off);

        if (lane == 0) {
            float v = tanhf(acc + xp[(size_t)t * HIDDEN + row] + bias);
            hs[(size_t)t * HIDDEN + row] = v;
            if (t == TSTEPS - 1) h_final[row] = v;
        }
        __syncthreads();

        if (tid == 0) {
            __threadfence();
            unsigned long long tk = atomicAdd(&g_bar_cnt, 1ULL);
            if (t == 0) base = (tk / TOTAL) * TOTAL;
            const unsigned long long target =
                base + (unsigned long long)(t + 1) * RNN_NB;
            while (*(volatile unsigned long long*)&g_bar_cnt < target) { }
            __threadfence();
        }
        __syncthreads();
    }
}

// ===========================================================================
// Logits GEMM — R11 kernel with ONE change: product-type-OUTER MMA ordering.
// All 48 fragment regs preloaded per s-slice; the three product passes
// (hh, lh, hl) each issue 16 independent MMAs -> same-accumulator reuse
// distance 16 (covers HMMA latency), instead of R11's 3-deep dependent
// chains. lb(256,1) keeps ~255 regs available -> no spill (~155 live).
// ===========================================================================
#define TCB_M 128
#define TCB_N 128
#define TCB_K 32
#define NCH   (HIDDEN / TCB_K)            // 32
#define PITCH 80                          // 64B data + 16B pad per 32-elem row
#define MATB  (TCB_M * PITCH)             // 10240 bytes per matrix tile
#define BUFB  (4 * MATB)                  // AH, AL, BH, BL
#define MMA_SMEM (2 * BUFB + 512)         // + bias staging

__global__ __launch_bounds__(256, 1)
void mma_logits_kernel(const float* __restrict__ A,    // hs    [2048,1024]
                       const float* __restrict__ B,    // W_out [50257,1024]
                       const float* __restrict__ bias, // [50257]
                       float* __restrict__ C)          // [2048,50257]
{
    extern __shared__ char sm[];
    float* bias_s = (float*)(sm + 2 * BUFB);
    const uint32_t sbase = smem_u32(sm);

    const int tid   = threadIdx.x;
    const int wid   = tid >> 5;
    const int lane  = tid & 31;
    const int warpm = wid >> 2;            // 0..1 -> 64-row slab
    const int warpn = wid & 3;             // 0..3 -> 32-col slab
    const int row0  = blockIdx.x * TCB_M;
    const int col0  = blockIdx.y * TCB_N;

    if (tid < TCB_N) {
        int c = col0 + tid;
        bias_s[tid] = (c < VOCAB) ? bias[c] : 0.0f;
    }

    const float* Abase = A + (size_t)row0 * HIDDEN;
    const float* Bbase = B + (size_t)col0 * HIDDEN;

    float acc[4][4][4];
#pragma unroll
    for (int i = 0; i < 4; i++)
#pragma unroll
        for (int j = 0; j < 4; j++)
#pragma unroll
            for (int r = 0; r < 4; r++) acc[i][j][r] = 0.0f;

    float4 aR[4], bR[4];

    auto ldg_chunk = [&](int k) {
        const int k0 = k * TCB_K;
#pragma unroll
        for (int i = 0; i < 4; i++) {
            int lin = tid + 256 * i;
            int r = lin >> 3, c4 = lin & 7;
            aR[i] = *(const float4*)(Abase + (size_t)r * HIDDEN + k0 + c4 * 4);
            if (col0 + r < VOCAB)
                bR[i] = *(const float4*)(Bbase + (size_t)r * HIDDEN + k0 + c4 * 4);
            else
                bR[i] = make_float4(0.f, 0.f, 0.f, 0.f);
        }
    };

    auto sts_chunk = [&](int buf) {
        char* base = sm + buf * BUFB;
#pragma unroll
        for (int i = 0; i < 4; i++) {
            int lin = tid + 256 * i;
            int r = lin >> 3, c4 = lin & 7;
            int off = r * PITCH + c4 * 8;
            uint2 hi, lo;
            split4(aR[i], hi, lo);
            *(uint2*)(base + off)        = hi;
            *(uint2*)(base + MATB + off) = lo;
            split4(bR[i], hi, lo);
            *(uint2*)(base + 2 * MATB + off) = hi;
            *(uint2*)(base + 3 * MATB + off) = lo;
        }
    };

    auto mma_chunk = [&](int buf) {
        const uint32_t base = sbase + buf * BUFB;
        const uint32_t lrow = lane & 15;
        const uint32_t lhalf = (lane >> 4) * 16;
#pragma unroll
        for (int s = 0; s < 2; s++) {
            uint32_t ah[4][4], al[4][4], bh[2][4], bl[2][4];
#pragma unroll
            for (int mf = 0; mf < 4; mf++) {
                uint32_t ad = base + (warpm * 64 + mf * 16 + lrow) * PITCH
                            + s * 32 + lhalf;
                LDSM_X4(ah[mf][0], ah[mf][1], ah[mf][2], ah[mf][3], ad);
                LDSM_X4(al[mf][0], al[mf][1], al[mf][2], al[mf][3], ad + MATB);
            }
#pragma unroll
            for (int p = 0; p < 2; p++) {
                uint32_t bd = base + 2 * MATB
                            + (warpn * 32 + p * 16 + lrow) * PITCH
                            + s * 32 + lhalf;
                LDSM_X4(bh[p][0], bh[p][1], bh[p][2], bh[p][3], bd);
                LDSM_X4(bl[p][0], bl[p][1], bl[p][2], bl[p][3], bd + MATB);
            }
            // pass 1: Ah x Bh — 16 independent MMAs
#pragma unroll
            for (int mf = 0; mf < 4; mf++)
#pragma unroll
                for (int nf = 0; nf < 4; nf++) {
                    const int p = nf >> 1, q = nf & 1;
                    MMA_BF16(acc[mf][nf], ah[mf][0], ah[mf][1], ah[mf][2], ah[mf][3],
                             bh[p][q], bh[p][q + 2]);
                }
            // pass 2: Al x Bh
#pragma unroll
            for (int mf = 0; mf < 4; mf++)
#pragma unroll
                for (int nf = 0; nf < 4; nf++) {
                    const int p = nf >> 1, q = nf & 1;
                    MMA_BF16(acc[mf][nf], al[mf][0], al[mf][1], al[mf][2], al[mf][3],
                             bh[p][q], bh[p][q + 2]);
                }
            // pass 3: Ah x Bl
#pragma unroll
            for (int mf = 0; mf < 4; mf++)
#pragma unroll
                for (int nf = 0; nf < 4; nf++) {
                    const int p = nf >> 1, q = nf & 1;
                    MMA_BF16(acc[mf][nf], ah[mf][0], ah[mf][1], ah[mf][2], ah[mf][3],
                             bl[p][q], bl[p][q + 2]);
                }
        }
    };

    ldg_chunk(0);
    sts_chunk(0);
    __syncthreads();

#pragma unroll 1
    for (int k = 0; k < NCH; k++) {
        if (k + 1 < NCH) ldg_chunk(k + 1);     // LDG overlapped with MMA
        mma_chunk(k & 1);
        if (k + 1 < NCH) sts_chunk((k + 1) & 1);
        __syncthreads();
    }

    // epilogue: acc frag m16n8 -> (row = lane/4 [+8], col = 2*(lane%4)+{0,1})
#pragma unroll
    for (int mf = 0; mf < 4; mf++) {
#pragma unroll
        for (int nf = 0; nf < 4; nf++) {
            const int mrow = row0 + warpm * 64 + mf * 16 + (lane >> 2);
            const int ncl  = warpn * 32 + nf * 8 + (lane & 3) * 2;
            const int col  = col0 + ncl;
            float* C0 = C + (size_t)mrow * VOCAB;
            float* C1 = C + (size_t)(mrow + 8) * VOCAB;
            if (col < VOCAB) {
                const float bv = bias_s[ncl];
                C0[col] = acc[mf][nf][0] + bv;
                C1[col] = acc[mf][nf][2] + bv;
            }
            if (col + 1 < VOCAB) {
                const float bv = bias_s[ncl + 1];
                C0[col + 1] = acc[mf][nf][1] + bv;
                C1[col + 1] = acc[mf][nf][3] + bv;
            }
        }
    }
}

// ===========================================================================
// launch
// ===========================================================================
extern "C" void kernel_launch(void* const* d_in, const int* in_sizes, int n_in,
                              void* d_out, int out_size)
{
    const int*   x     = (const int*)  d_in[0];
    const float* emb   = (const float*)d_in[1];
    const float* W_xh  = (const float*)d_in[2];
    const float* W_hh  = (const float*)d_in[3];
    const float* b_hh  = (const float*)d_in[4];
    const float* W_out = (const float*)d_in[5];
    const float* b_out = (const float*)d_in[6];

    float* logits  = (float*)d_out;
    float* h_final = (float*)d_out + (size_t)TSTEPS * VOCAB;

    float *xp, *hs;
    cudaGetSymbolAddress((void**)&xp, g_xp);
    cudaGetSymbolAddress((void**)&hs, g_hs);

    // 1) xp = emb[x] @ W_xh^T      (M=2048, N=1024, K=512)
    {
        dim3 grid(HIDDEN / 128, TSTEPS / 128);
        sgemm_nt_kernel<true><<<grid, 256>>>(emb, W_xh, nullptr, xp, x,
                                             TSTEPS, HIDDEN, EMBED);
    }

    // 2) sequential recurrence -> hs, h_final   (exact R11)
    rnn_recurrence_kernel<<<RNN_NB, RNN_NT>>>(xp, W_hh, b_hh, hs, h_final);

    // 3) logits = hs @ W_out^T + b_out  (R11 + outer MMA ordering)
    {
        cudaFuncSetAttribute(mma_logits_kernel,
                             cudaFuncAttributeMaxDynamicSharedMemorySize,
                             MMA_SMEM);
        dim3 grid(TSTEPS / TCB_M, (VOCAB + TCB_N - 1) / TCB_N); // 16 x 393
        mma_logits_kernel<<<grid, 256, MMA_SMEM>>>(hs, W_out, b_out, logits);
    }
}

// round 17
// speedup vs baseline: 1.6086x; 1.1640x over previous
#include <cuda_runtime.h>
#include <cuda_fp16.h>
#include <cstdint>

#define VOCAB   50257
#define EMBED   512
#define HIDDEN  1024
#define TSTEPS  2048

// Scratch (allocation-free rule: __device__ globals)
__device__ float g_xp[TSTEPS * HIDDEN];   // 8 MB: input projections
__device__ float g_hs[TSTEPS * HIDDEN];   // 8 MB: hidden states per step
__device__ unsigned long long g_bar_cnt;  // monotonic grid-barrier counter

// ===========================================================================
// helpers
// ===========================================================================
__device__ __forceinline__ uint32_t smem_u32(const void* p) {
    uint32_t a;
    asm("{ .reg .u64 t; cvta.to.shared.u64 t, %1; cvt.u32.u64 %0, t; }"
        : "=r"(a) : "l"(p));
    return a;
}

// pack two fp32 -> f16x2 (first arg -> low half)
__device__ __forceinline__ uint32_t pack_f16x2(float lo, float hi) {
    uint32_t r;
    asm("cvt.rn.f16x2.f32 %0, %1, %2;" : "=r"(r) : "f"(hi), "f"(lo));
    return r;
}
// convert float4 -> 4 fp16 packed in uint2
__device__ __forceinline__ uint2 cvt4_f16(float4 v) {
    return make_uint2(pack_f16x2(v.x, v.y), pack_f16x2(v.z, v.w));
}

#define LDSM_X4(r0, r1, r2, r3, addr)                                       \
    asm volatile("ldmatrix.sync.aligned.m8n8.x4.shared.b16 {%0,%1,%2,%3}, [%4];" \
                 : "=r"(r0), "=r"(r1), "=r"(r2), "=r"(r3) : "r"(addr))

#define MMA_F16(c, a0, a1, a2, a3, b0, b1)                                  \
    asm volatile("mma.sync.aligned.m16n8k16.row.col.f32.f16.f16.f32 "       \
                 "{%0,%1,%2,%3}, {%4,%5,%6,%7}, {%8,%9}, {%0,%1,%2,%3};"    \
                 : "+f"((c)[0]), "+f"((c)[1]), "+f"((c)[2]), "+f"((c)[3])   \
                 : "r"(a0), "r"(a1), "r"(a2), "r"(a3), "r"(b0), "r"(b1))

// ===========================================================================
// fp32 SGEMM (NT) — used only for the small xp = emb[x] @ W_xh^T GEMM
// ===========================================================================
template <bool GATHER>
__global__ __launch_bounds__(256, 2)
void sgemm_nt_kernel(const float* __restrict__ A,
                     const float* __restrict__ B,
                     const float* __restrict__ bias,
                     float* __restrict__ C,
                     const int* __restrict__ idx,
                     int M, int N, int K)
{
    const int BM = 128, BN = 128, BK = 8;
    __shared__ float As[BK][BM];
    __shared__ float Bs[BK][BN];

    const int tid  = threadIdx.x;
    const int row0 = blockIdx.y * BM;
    const int col0 = blockIdx.x * BN;

    const int lr = tid >> 1;
    const int lc = (tid & 1) * 4;

    const int arow_g = row0 + lr;
    const float* Arow = A + (size_t)(GATHER ? idx[arow_g] : arow_g) * K;

    const int brow_g = col0 + lr;
    const float* Brow = B + (size_t)brow_g * K;
    const bool bvalid = (brow_g < N);

    const int tx = tid & 15;
    const int ty = tid >> 4;

    float acc[8][8];
#pragma unroll
    for (int i = 0; i < 8; i++)
#pragma unroll
        for (int j = 0; j < 8; j++) acc[i][j] = 0.0f;

    for (int k0 = 0; k0 < K; k0 += BK) {
        float4 av = *(const float4*)(Arow + k0 + lc);
        float4 bv = make_float4(0.f, 0.f, 0.f, 0.f);
        if (bvalid) bv = *(const float4*)(Brow + k0 + lc);

        As[lc + 0][lr] = av.x; As[lc + 1][lr] = av.y;
        As[lc + 2][lr] = av.z; As[lc + 3][lr] = av.w;
        Bs[lc + 0][lr] = bv.x; Bs[lc + 1][lr] = bv.y;
        Bs[lc + 2][lr] = bv.z; Bs[lc + 3][lr] = bv.w;
        __syncthreads();

#pragma unroll
        for (int k = 0; k < BK; k++) {
            float af[8], bf[8];
#pragma unroll
            for (int i = 0; i < 8; i++) af[i] = As[k][ty * 8 + i];
#pragma unroll
            for (int j = 0; j < 8; j++) bf[j] = Bs[k][tx * 8 + j];
#pragma unroll
            for (int i = 0; i < 8; i++)
#pragma unroll
                for (int j = 0; j < 8; j++) acc[i][j] += af[i] * bf[j];
        }
        __syncthreads();
    }

#pragma unroll
    for (int i = 0; i < 8; i++) {
        const int row = row0 + ty * 8 + i;
        float* Crow = C + (size_t)row * N;
#pragma unroll
        for (int j = 0; j < 8; j++) {
            const int col = col0 + tx * 8 + j;
            if (col < N) {
                float v = acc[i][j];
                if (bias) v += bias[col];
                Crow[col] = v;
            }
        }
    }
}

// ===========================================================================
// Recurrence — EXACT R11 version (best measured): 64 blocks x 512 threads,
// W_hh rows in registers, replay-safe monotonic-counter grid barrier.
// ===========================================================================
#define RNN_NB 64
#define RNN_NT 512

__global__ __launch_bounds__(RNN_NT, 1)
void rnn_recurrence_kernel(const float* __restrict__ xp,
                           const float* __restrict__ W_hh,
                           const float* __restrict__ b_hh,
                           float* __restrict__ hs,
                           float* __restrict__ h_final)
{
    __shared__ float hsm[HIDDEN];

    const int tid  = threadIdx.x;
    const int warp = tid >> 5;
    const int lane = tid & 31;
    const int row  = blockIdx.x * 16 + warp;

    float w[32];
    const float* Wrow = W_hh + (size_t)row * HIDDEN;
#pragma unroll
    for (int k = 0; k < 32; k++) w[k] = Wrow[lane + 32 * k];
    const float bias = b_hh[row];

    const unsigned long long TOTAL = (unsigned long long)TSTEPS * RNN_NB;
    unsigned long long base = 0;

    for (int t = 0; t < TSTEPS; t++) {
        if (t == 0) {
            hsm[tid]       = 0.0f;
            hsm[tid + 512] = 0.0f;
        } else {
            const float* hprev = hs + (size_t)(t - 1) * HIDDEN;
            hsm[tid]       = hprev[tid];
            hsm[tid + 512] = hprev[tid + 512];
        }
        __syncthreads();

        float acc = 0.0f;
#pragma unroll
        for (int k = 0; k < 32; k++) acc += w[k] * hsm[lane + 32 * k];
#pragma unroll
        for (int off = 16; off > 0; off >>= 1)
            acc += __shfl_down_sync(0xffffffffu, acc, off);

        if (lane == 0) {
            float v = tanhf(acc + xp[(size_t)t * HIDDEN + row] + bias);
            hs[(size_t)t * HIDDEN + row] = v;
            if (t == TSTEPS - 1) h_final[row] = v;
        }
        __syncthreads();

        if (tid == 0) {
            __threadfence();
            unsigned long long tk = atomicAdd(&g_bar_cnt, 1ULL);
            if (t == 0) base = (tk / TOTAL) * TOTAL;
            const unsigned long long target =
                base + (unsigned long long)(t + 1) * RNN_NB;
            while (*(volatile unsigned long long*)&g_bar_cnt < target) { }
            __threadfence();
        }
        __syncthreads();
    }
}

// ===========================================================================
// Logits GEMM — SINGLE-product fp16 mma.sync (was bf16 3-product hi/lo).
// C[2048,50257] = hs @ W_out^T + b_out.
// fp16 11-bit mantissa -> aggregate rel_err ~1e-4 (threshold 1e-3).
// Range safe: hs = tanh in (-1,1); W_out in (-1/32, 1/32); fp32 accum.
// R11 skeleton: CTA 128x128, BK=32, PITCH=80, register prefetch, 1 CTA/SM.
// 3x fewer MMAs, half the smem (41KB), 24 frag regs.
// ===========================================================================
#define TCB_M 128
#define TCB_N 128
#define TCB_K 32
#define NCH   (HIDDEN / TCB_K)            // 32
#define PITCH 80                          // 64B data + 16B pad per 32-elem row
#define MATB  (TCB_M * PITCH)             // 10240 bytes per matrix tile
#define BUFB  (2 * MATB)                  // A, B  = 20480
#define MMA_SMEM (2 * BUFB + 512)         // 41472

__global__ __launch_bounds__(256, 1)
void mma_logits_kernel(const float* __restrict__ A,    // hs    [2048,1024]
                       const float* __restrict__ B,    // W_out [50257,1024]
                       const float* __restrict__ bias, // [50257]
                       float* __restrict__ C)          // [2048,50257]
{
    extern __shared__ char sm[];
    float* bias_s = (float*)(sm + 2 * BUFB);
    const uint32_t sbase = smem_u32(sm);

    const int tid   = threadIdx.x;
    const int wid   = tid >> 5;
    const int lane  = tid & 31;
    const int warpm = wid >> 2;            // 0..1 -> 64-row slab
    const int warpn = wid & 3;             // 0..3 -> 32-col slab
    const int row0  = blockIdx.x * TCB_M;
    const int col0  = blockIdx.y * TCB_N;

    if (tid < TCB_N) {
        int c = col0 + tid;
        bias_s[tid] = (c < VOCAB) ? bias[c] : 0.0f;
    }

    const float* Abase = A + (size_t)row0 * HIDDEN;
    const float* Bbase = B + (size_t)col0 * HIDDEN;

    float acc[4][4][4];
#pragma unroll
    for (int i = 0; i < 4; i++)
#pragma unroll
        for (int j = 0; j < 4; j++)
#pragma unroll
            for (int r = 0; r < 4; r++) acc[i][j][r] = 0.0f;

    float4 aR[4], bR[4];

    auto ldg_chunk = [&](int k) {
        const int k0 = k * TCB_K;
#pragma unroll
        for (int i = 0; i < 4; i++) {
            int lin = tid + 256 * i;
            int r = lin >> 3, c4 = lin & 7;
            aR[i] = *(const float4*)(Abase + (size_t)r * HIDDEN + k0 + c4 * 4);
            if (col0 + r < VOCAB)
                bR[i] = *(const float4*)(Bbase + (size_t)r * HIDDEN + k0 + c4 * 4);
            else
                bR[i] = make_float4(0.f, 0.f, 0.f, 0.f);
        }
    };

    auto sts_chunk = [&](int buf) {
        char* base = sm + buf * BUFB;
#pragma unroll
        for (int i = 0; i < 4; i++) {
            int lin = tid + 256 * i;
            int r = lin >> 3, c4 = lin & 7;
            int off = r * PITCH + c4 * 8;
            *(uint2*)(base + off)        = cvt4_f16(aR[i]);
            *(uint2*)(base + MATB + off) = cvt4_f16(bR[i]);
        }
    };

    auto mma_chunk = [&](int buf) {
        const uint32_t base = sbase + buf * BUFB;
        const uint32_t lrow = lane & 15;
        const uint32_t lhalf = (lane >> 4) * 16;
#pragma unroll
        for (int s = 0; s < 2; s++) {           // two k16 slices of BK=32
            uint32_t ah[4][4], bh[2][4];
#pragma unroll
            for (int mf = 0; mf < 4; mf++) {
                uint32_t ad = base + (warpm * 64 + mf * 16 + lrow) * PITCH
                            + s * 32 + lhalf;
                LDSM_X4(ah[mf][0], ah[mf][1], ah[mf][2], ah[mf][3], ad);
            }
#pragma unroll
            for (int p = 0; p < 2; p++) {
                uint32_t bd = base + MATB
                            + (warpn * 32 + p * 16 + lrow) * PITCH
                            + s * 32 + lhalf;
                LDSM_X4(bh[p][0], bh[p][1], bh[p][2], bh[p][3], bd);
            }
            // 16 independent MMAs
#pragma unroll
            for (int mf = 0; mf < 4; mf++)
#pragma unroll
                for (int nf = 0; nf < 4; nf++) {
                    const int p = nf >> 1, q = nf & 1;
                    MMA_F16(acc[mf][nf], ah[mf][0], ah[mf][1], ah[mf][2], ah[mf][3],
                            bh[p][q], bh[p][q + 2]);
                }
        }
    };

    ldg_chunk(0);
    sts_chunk(0);
    __syncthreads();

#pragma unroll 1
    for (int k = 0; k < NCH; k++) {
        if (k + 1 < NCH) ldg_chunk(k + 1);     // LDG overlapped with MMA
        mma_chunk(k & 1);
        if (k + 1 < NCH) sts_chunk((k + 1) & 1);
        __syncthreads();
    }

    // epilogue: acc frag m16n8 -> (row = lane/4 [+8], col = 2*(lane%4)+{0,1})
#pragma unroll
    for (int mf = 0; mf < 4; mf++) {
#pragma unroll
        for (int nf = 0; nf < 4; nf++) {
            const int mrow = row0 + warpm * 64 + mf * 16 + (lane >> 2);
            const int ncl  = warpn * 32 + nf * 8 + (lane & 3) * 2;
            const int col  = col0 + ncl;
            float* C0 = C + (size_t)mrow * VOCAB;
            float* C1 = C + (size_t)(mrow + 8) * VOCAB;
            if (col < VOCAB) {
                const float bv = bias_s[ncl];
                C0[col] = acc[mf][nf][0] + bv;
                C1[col] = acc[mf][nf][2] + bv;
            }
            if (col + 1 < VOCAB) {
                const float bv = bias_s[ncl + 1];
                C0[col + 1] = acc[mf][nf][1] + bv;
                C1[col + 1] = acc[mf][nf][3] + bv;
            }
        }
    }
}

// ===========================================================================
// launch
// ===========================================================================
extern "C" void kernel_launch(void* const* d_in, const int* in_sizes, int n_in,
                              void* d_out, int out_size)
{
    const int*   x     = (const int*)  d_in[0];
    const float* emb   = (const float*)d_in[1];
    const float* W_xh  = (const float*)d_in[2];
    const float* W_hh  = (const float*)d_in[3];
    const float* b_hh  = (const float*)d_in[4];
    const float* W_out = (const float*)d_in[5];
    const float* b_out = (const float*)d_in[6];

    float* logits  = (float*)d_out;
    float* h_final = (float*)d_out + (size_t)TSTEPS * VOCAB;

    float *xp, *hs;
    cudaGetSymbolAddress((void**)&xp, g_xp);
    cudaGetSymbolAddress((void**)&hs, g_hs);

    // 1) xp = emb[x] @ W_xh^T      (M=2048, N=1024, K=512)
    {
        dim3 grid(HIDDEN / 128, TSTEPS / 128);
        sgemm_nt_kernel<true><<<grid, 256>>>(emb, W_xh, nullptr, xp, x,
                                             TSTEPS, HIDDEN, EMBED);
    }

    // 2) sequential recurrence -> hs, h_final   (exact R11)
    rnn_recurrence_kernel<<<RNN_NB, RNN_NT>>>(xp, W_hh, b_hh, hs, h_final);

    // 3) logits = hs @ W_out^T + b_out  (single-product fp16 mma.sync)
    {
        cudaFuncSetAttribute(mma_logits_kernel,
                             cudaFuncAttributeMaxDynamicSharedMemorySize,
                             MMA_SMEM);
        dim3 grid(TSTEPS / TCB_M, (VOCAB + TCB_N - 1) / TCB_N); // 16 x 393
        mma_logits_kernel<<<grid, 256, MMA_SMEM>>>(hs, W_out, b_out, logits);
    }
}